// round 9
// baseline (speedup 1.0000x reference)
#include <cuda_runtime.h>
#include <math.h>

// ---------------------------------------------------------------------------
// DiMap SPD pipeline, round 8.
// ONE-SIDED Jacobi on explicit Cholesky-derived factors: the eigenvector
// accumulation pass of two-sided Jacobi disappears (columns of the rotated
// factor ARE u_i * sqrt(lambda_i)). f(C) = sum f(l_i)/l_i * w_i w_i^T.
// k_pair emits the barycenter factor F_b (g_fbuf) so k_bn1's matrix
// factorizes with a single matmul: Li0 bary Li0^T = (Li0 F_b)(Li0 F_b)^T.
// ---------------------------------------------------------------------------

#define LD 65           // smem row stride: conflict-free rows AND columns
#define SLOT (64 * LD)  // one 64x64 matrix slot (4160 floats)
#define TAIL 384        // fv64 cb32 sb32 pqb32 red24 vec64 nrm64
#define MAXSWEEP 10
#define JTOL1S 2e-7f
#define NSMAX 13

// --- scratch (allocation-free: __device__ globals) -------------------------
__device__ float g_abuf[16777216];  // 4096 x 64 x 64  bary matrices
__device__ float g_fbuf[16777216];  // 4096 x 64 x 64  bary factors
__device__ float g_lbuf[16777216];  // 4096 x 64 x 64  log matrices
__device__ float g_part[32768];     // 8 x 4096 partial sums
__device__ float g_w01[2];
__device__ float g_G0[4096];
__device__ float g_Sbar[4096];
__device__ float g_L0[4096];        // chol factor of G0 (dense lower)
__device__ float g_Li0[4096];       // L0^{-1} (dense lower)
__device__ float g_T[4096];

// round-robin tournament pairing: 63 rounds x 32 disjoint pairs
__device__ __forceinline__ void pairpq(int rnd, int k, int& p, int& q) {
    if (k == 0) { p = 63; q = rnd; }
    else {
        int a = rnd + k; if (a >= 63) a -= 63;
        int b = rnd - k; if (b < 0)  b += 63;
        p = a; q = b;
    }
}

// ---------------------------------------------------------------------------
__device__ float block_sum(float v, float* red) {
    const int tid = threadIdx.x;
    #pragma unroll
    for (int o = 16; o > 0; o >>= 1) v += __shfl_xor_sync(0xFFFFFFFFu, v, o);
    __syncthreads();
    if ((tid & 31) == 0) red[tid >> 5] = v;
    __syncthreads();
    if (tid == 0) {
        float s = 0.0f;
        #pragma unroll
        for (int w = 0; w < 8; ++w) s += red[w];
        red[8] = s;
    }
    __syncthreads();
    float r = red[8];
    __syncthreads();
    return r;
}

// spectral-norm estimate via 6 power iterations (k_bary only)
__device__ float spec_est(const float* A, float* vec, float* red) {
    const int tid = threadIdx.x;
    if (tid < 64) vec[tid] = 1.0f;
    __syncthreads();
    float m = 1.0f;
    for (int it = 0; it < 6; ++it) {
        float y = 0.0f;
        if (tid < 64) {
            #pragma unroll 8
            for (int k = 0; k < 64; ++k) y += A[tid * LD + k] * vec[k];
            float a = fabsf(y);
            #pragma unroll
            for (int o = 16; o > 0; o >>= 1)
                a = fmaxf(a, __shfl_xor_sync(0xFFFFFFFFu, a, o));
            if ((tid & 31) == 0) red[tid >> 5] = a;
        }
        __syncthreads();
        m = fmaxf(red[0], red[1]);
        if (tid < 64) vec[tid] = y / m;
        __syncthreads();
    }
    return m;
}

// ---------------------------------------------------------------------------
// Unscaled LDL^T Cholesky elimination (both triangles kept symmetric).
// Exit: W[r][j] (r>j) = Ltil[r][j]*D[j]; W[j][j] = D[j].
// ---------------------------------------------------------------------------
__device__ void chol_u(float* W) {
    const int tid = threadIdx.x;
    for (int j = 0; j < 64; ++j) {
        float dinv = 1.0f / W[j * LD + j];
        #pragma unroll
        for (int it = 0; it < 16; ++it) {
            int i = tid + it * 256;
            int r = i >> 6, c = i & 63;
            if (r > j && c > j)
                W[r * LD + c] -= W[r * LD + j] * W[c * LD + j] * dinv;
        }
        __syncthreads();
    }
}

// X <- Ltil^{-1} X  (unit-lower, factors packed in W)
__device__ void trsm_left(const float* W, float* X) {
    const int tid = threadIdx.x;
    for (int i = 0; i < 64; ++i) {
        float dinv = 1.0f / W[i * LD + i];
        #pragma unroll
        for (int it = 0; it < 16; ++it) {
            int idx = tid + it * 256;
            int r = idx >> 6, c = idx & 63;
            if (r > i)
                X[r * LD + c] -= (W[r * LD + i] * dinv) * X[i * LD + c];
        }
        __syncthreads();
    }
}

// ---------------------------------------------------------------------------
// One-sided Jacobi on factor W (64x64, column layout). 256 threads.
// Orthogonalizes columns: on exit column i = u_i * sqrt(l_i), nrm[i] = l_i.
// ---------------------------------------------------------------------------
__device__ void jacobi1s(float* W, float* nrm, float* cb, float* sb,
                         int* pqb, float* red) {
    const int tid = threadIdx.x;
    const int k  = tid >> 3;   // pair id (0..31) for dot stage
    const int jj = tid & 7;    // sub-lane within pair group

    // initial column norms
    if (tid < 64) {
        float s = 0.0f;
        #pragma unroll 8
        for (int r = 0; r < 64; ++r) { float v = W[r * LD + tid]; s += v * v; }
        nrm[tid] = s;
    }
    __syncthreads();

    for (int sw = 0; sw < MAXSWEEP; ++sw) {
        float gsum = 0.0f;   // accumulated gamma^2 (only jj==0 threads)
        for (int rnd = 0; rnd < 63; ++rnd) {
            int p, q; pairpq(rnd, k, p, q);
            // gamma = w_p . w_q  (8 threads per pair)
            float part = 0.0f;
            #pragma unroll
            for (int r8 = 0; r8 < 8; ++r8) {
                int r = jj + r8 * 8;
                part += W[r * LD + p] * W[r * LD + q];
            }
            part += __shfl_down_sync(0xFFFFFFFFu, part, 4);
            part += __shfl_down_sync(0xFFFFFFFFu, part, 2);
            part += __shfl_down_sync(0xFFFFFFFFu, part, 1);
            if (jj == 0) {
                float gam = part;
                float al = nrm[p], be = nrm[q];
                float c = 1.0f, s = 0.0f;
                if (fabsf(gam) > 1e-37f) {
                    float tau = (be - al) / (2.0f * gam);
                    float t = copysignf(1.0f, tau) /
                              (fabsf(tau) + sqrtf(1.0f + tau * tau));
                    c = rsqrtf(1.0f + t * t);
                    s = t * c;
                    float cs = c * s;
                    nrm[p] = c * c * al - 2.0f * cs * gam + s * s * be;
                    nrm[q] = s * s * al + 2.0f * cs * gam + c * c * be;
                }
                cb[k] = c; sb[k] = s;
                pqb[k] = p | (q << 8);
                gsum += gam * gam;
            }
            __syncthreads();
            // rotate columns: 2048 (row, pair) cells, 8 per thread
            #pragma unroll
            for (int it = 0; it < 8; ++it) {
                int ci = tid + it * 256;
                int m = ci >> 6, row = ci & 63;
                int pqm = pqb[m];
                int pm = pqm & 255, qm = pqm >> 8;
                float cm = cb[m], smv = sb[m];
                float vp = W[row * LD + pm], vq = W[row * LD + qm];
                W[row * LD + pm] = cm * vp - smv * vq;
                W[row * LD + qm] = smv * vp + cm * vq;
            }
            __syncthreads();
        }
        // convergence: sum of gamma^2 over sweep vs sum of lambda^2
        float tot = gsum;
        #pragma unroll
        for (int o = 16; o > 0; o >>= 1)
            tot += __shfl_xor_sync(0xFFFFFFFFu, tot, o);
        float dia = 0.0f;
        if (tid < 64) { float l = nrm[tid]; dia = l * l; }
        #pragma unroll
        for (int o = 16; o > 0; o >>= 1)
            dia += __shfl_xor_sync(0xFFFFFFFFu, dia, o);
        __syncthreads();
        if ((tid & 31) == 0) { red[tid >> 5] = tot; red[8 + (tid >> 5)] = dia; }
        __syncthreads();
        if (tid == 0) {
            float to = 0.0f, td = 0.0f;
            #pragma unroll
            for (int w = 0; w < 8; ++w) { to += red[w]; td += red[8 + w]; }
            red[16] = (to <= JTOL1S * td + 1e-30f) ? 1.0f : 0.0f;
        }
        __syncthreads();
        bool done = (red[16] != 0.0f);
        __syncthreads();
        if (done) break;
    }
    // exact final norms (insurance against incremental drift)
    if (tid < 64) {
        float s = 0.0f;
        #pragma unroll 8
        for (int r = 0; r < 64; ++r) { float v = W[r * LD + tid]; s += v * v; }
        nrm[tid] = s;
    }
    __syncthreads();
}

// ---------------------------------------------------------------------------
// 64x64 matmuls. 256 threads, 4x4 tile per thread.
// ---------------------------------------------------------------------------
__device__ void mm_nn(float* C, const float* A, const float* B) {
    const int t = threadIdx.x;
    const int i0 = (t >> 4) << 2, j0 = (t & 15) << 2;
    float acc[4][4];
    #pragma unroll
    for (int r = 0; r < 4; ++r)
        #pragma unroll
        for (int c = 0; c < 4; ++c) acc[r][c] = 0.0f;
    #pragma unroll 4
    for (int k = 0; k < 64; ++k) {
        float a[4], b[4];
        #pragma unroll
        for (int r = 0; r < 4; ++r) a[r] = A[(i0 + r) * LD + k];
        #pragma unroll
        for (int c = 0; c < 4; ++c) b[c] = B[k * LD + j0 + c];
        #pragma unroll
        for (int r = 0; r < 4; ++r)
            #pragma unroll
            for (int c = 0; c < 4; ++c) acc[r][c] += a[r] * b[c];
    }
    __syncthreads();
    #pragma unroll
    for (int r = 0; r < 4; ++r)
        #pragma unroll
        for (int c = 0; c < 4; ++c) C[(i0 + r) * LD + j0 + c] = acc[r][c];
    __syncthreads();
}

// C(smem) = A * B^T
__device__ void mm_nt(float* C, const float* A, const float* B) {
    const int t = threadIdx.x;
    const int i0 = (t >> 4) << 2, j0 = (t & 15) << 2;
    float acc[4][4];
    #pragma unroll
    for (int r = 0; r < 4; ++r)
        #pragma unroll
        for (int c = 0; c < 4; ++c) acc[r][c] = 0.0f;
    #pragma unroll 4
    for (int k = 0; k < 64; ++k) {
        float a[4], b[4];
        #pragma unroll
        for (int r = 0; r < 4; ++r) a[r] = A[(i0 + r) * LD + k];
        #pragma unroll
        for (int c = 0; c < 4; ++c) b[c] = B[(j0 + c) * LD + k];
        #pragma unroll
        for (int r = 0; r < 4; ++r)
            #pragma unroll
            for (int c = 0; c < 4; ++c) acc[r][c] += a[r] * b[c];
    }
    __syncthreads();
    #pragma unroll
    for (int r = 0; r < 4; ++r)
        #pragma unroll
        for (int c = 0; c < 4; ++c) C[(i0 + r) * LD + j0 + c] = acc[r][c];
    __syncthreads();
}

__device__ void mm_nn_g(float* Cg, const float* A, const float* B) {
    const int t = threadIdx.x;
    const int i0 = (t >> 4) << 2, j0 = (t & 15) << 2;
    float acc[4][4];
    #pragma unroll
    for (int r = 0; r < 4; ++r)
        #pragma unroll
        for (int c = 0; c < 4; ++c) acc[r][c] = 0.0f;
    #pragma unroll 4
    for (int k = 0; k < 64; ++k) {
        float a[4], b[4];
        #pragma unroll
        for (int r = 0; r < 4; ++r) a[r] = A[(i0 + r) * LD + k];
        #pragma unroll
        for (int c = 0; c < 4; ++c) b[c] = B[k * LD + j0 + c];
        #pragma unroll
        for (int r = 0; r < 4; ++r)
            #pragma unroll
            for (int c = 0; c < 4; ++c) acc[r][c] += a[r] * b[c];
    }
    #pragma unroll
    for (int r = 0; r < 4; ++r)
        #pragma unroll
        for (int c = 0; c < 4; ++c) Cg[(i0 + r) * 64 + j0 + c] = acc[r][c];
    __syncthreads();
}

__device__ void mm_nt_g(float* Cg, const float* A, const float* B) {
    const int t = threadIdx.x;
    const int i0 = (t >> 4) << 2, j0 = (t & 15) << 2;
    float acc[4][4];
    #pragma unroll
    for (int r = 0; r < 4; ++r)
        #pragma unroll
        for (int c = 0; c < 4; ++c) acc[r][c] = 0.0f;
    #pragma unroll 4
    for (int k = 0; k < 64; ++k) {
        float a[4], b[4];
        #pragma unroll
        for (int r = 0; r < 4; ++r) a[r] = A[(i0 + r) * LD + k];
        #pragma unroll
        for (int c = 0; c < 4; ++c) b[c] = B[(j0 + c) * LD + k];
        #pragma unroll
        for (int r = 0; r < 4; ++r)
            #pragma unroll
            for (int c = 0; c < 4; ++c) acc[r][c] += a[r] * b[c];
    }
    #pragma unroll
    for (int r = 0; r < 4; ++r)
        #pragma unroll
        for (int c = 0; c < 4; ++c) Cg[(i0 + r) * 64 + j0 + c] = acc[r][c];
    __syncthreads();
}

// C = L * V, with L[r][k] = W[r][k]*dsc[k] for k<=r (0 above diag).
__device__ void mm_ltn(float* C, const float* W, const float* dsc,
                       const float* V) {
    const int t = threadIdx.x;
    const int i0 = (t >> 4) << 2, j0 = (t & 15) << 2;
    float acc[4][4];
    #pragma unroll
    for (int r = 0; r < 4; ++r)
        #pragma unroll
        for (int c = 0; c < 4; ++c) acc[r][c] = 0.0f;
    #pragma unroll 4
    for (int k = 0; k < 64; ++k) {
        float f = dsc[k];
        float a[4], b[4];
        #pragma unroll
        for (int r = 0; r < 4; ++r)
            a[r] = (k <= i0 + r) ? W[(i0 + r) * LD + k] * f : 0.0f;
        #pragma unroll
        for (int c = 0; c < 4; ++c) b[c] = V[k * LD + j0 + c];
        #pragma unroll
        for (int r = 0; r < 4; ++r)
            #pragma unroll
            for (int c = 0; c < 4; ++c) acc[r][c] += a[r] * b[c];
    }
    __syncthreads();
    #pragma unroll
    for (int r = 0; r < 4; ++r)
        #pragma unroll
        for (int c = 0; c < 4; ++c) C[(i0 + r) * LD + j0 + c] = acc[r][c];
    __syncthreads();
}

// Cg(gmem) = V diag(f) V^T
__device__ void mm_recon_g(float* Cg, const float* V, const float* f) {
    const int t = threadIdx.x;
    const int i0 = (t >> 4) << 2, j0 = (t & 15) << 2;
    float acc[4][4];
    #pragma unroll
    for (int r = 0; r < 4; ++r)
        #pragma unroll
        for (int c = 0; c < 4; ++c) acc[r][c] = 0.0f;
    #pragma unroll 4
    for (int k = 0; k < 64; ++k) {
        float fk = f[k];
        float a[4], b[4];
        #pragma unroll
        for (int r = 0; r < 4; ++r) a[r] = V[(i0 + r) * LD + k] * fk;
        #pragma unroll
        for (int c = 0; c < 4; ++c) b[c] = V[(j0 + c) * LD + k];
        #pragma unroll
        for (int r = 0; r < 4; ++r)
            #pragma unroll
            for (int c = 0; c < 4; ++c) acc[r][c] += a[r] * b[c];
    }
    #pragma unroll
    for (int r = 0; r < 4; ++r)
        #pragma unroll
        for (int c = 0; c < 4; ++c) Cg[(i0 + r) * 64 + j0 + c] = acc[r][c];
    __syncthreads();
}

__device__ void gload(float* M, const float* g) {
    for (int i = threadIdx.x; i < 4096; i += 256)
        M[(i >> 6) * LD + (i & 63)] = g[i];
    __syncthreads();
}

// ---------------------------------------------------------------------------
// Coupled Newton-Schulz + sexpm (k_bary only)
// ---------------------------------------------------------------------------
__device__ void ns_sqrt(float* Y, float* Z, float* T, float* red) {
    const int tid = threadIdx.x;
    for (int it = 0; it < NSMAX; ++it) {
        mm_nn(T, Z, Y);
        float mx = 0.0f;
        for (int i = tid; i < 4096; i += 256) {
            int r = i >> 6, c = i & 63;
            float v = T[r * LD + c];
            float t = ((r == c) ? 1.5f : 0.0f) - 0.5f * v;
            T[r * LD + c] = t;
            mx = fmaxf(mx, fabsf(t - ((r == c) ? 1.0f : 0.0f)));
        }
        __syncthreads();
        #pragma unroll
        for (int o = 16; o > 0; o >>= 1)
            mx = fmaxf(mx, __shfl_xor_sync(0xFFFFFFFFu, mx, o));
        if ((tid & 31) == 0) red[tid >> 5] = mx;
        __syncthreads();
        if (tid == 0) {
            float g = 0.0f;
            #pragma unroll
            for (int w = 0; w < 8; ++w) g = fmaxf(g, red[w]);
            red[8] = g;
        }
        __syncthreads();
        float g = red[8];
        __syncthreads();
        if (g < 3e-8f) break;
        mm_nn(Y, Y, T);
        mm_nn(Z, T, Z);
    }
}

__device__ void sexpm(float* B, float* Q, float* T, float* red) {
    const int tid = threadIdx.x;
    float s2 = 0.0f;
    for (int i = tid; i < 4096; i += 256) {
        float v = B[(i >> 6) * LD + (i & 63)];
        s2 += v * v;
    }
    float fn = sqrtf(block_sum(s2, red));
    int s = 0; float f = fn;
    while (f > 0.5f && s < 40) { f *= 0.5f; ++s; }
    float scale = ldexpf(1.0f, -s);
    for (int i = tid; i < 4096; i += 256)
        B[(i >> 6) * LD + (i & 63)] *= scale;
    __syncthreads();
    for (int i = tid; i < 4096; i += 256) {
        int r = i >> 6, c = i & 63;
        Q[r * LD + c] = ((r == c) ? 1.0f : 0.0f) + 0.1f * B[r * LD + c];
    }
    __syncthreads();
    for (int k = 9; k >= 1; --k) {
        mm_nn(T, B, Q);
        float inv = 1.0f / (float)k;
        for (int i = tid; i < 4096; i += 256) {
            int r = i >> 6, c = i & 63;
            Q[r * LD + c] = ((r == c) ? 1.0f : 0.0f) + inv * T[r * LD + c];
        }
        __syncthreads();
    }
    for (int i = 0; i < s; ++i) mm_nn(Q, Q, Q);
}

// ---------------------------------------------------------------------------
__global__ void k_softmax(const float* __restrict__ wv) {
    float a = wv[0], b = wv[1];
    float m = fmaxf(a, b);
    float ea = expf(a - m), eb = expf(b - m);
    float inv = 1.0f / (ea + eb);
    g_w01[0] = ea * inv;
    g_w01[1] = eb * inv;
}

// ---------------------------------------------------------------------------
// K2: pair barycenter. One-sided Jacobi on F_c = Ltil_G^{-1} Lx scaled.
// Emits bary (g_abuf) and its factor F_b (g_fbuf).
// ---------------------------------------------------------------------------
__global__ void __launch_bounds__(256, 4) k_pair(const float* __restrict__ x) {
    extern __shared__ float sm[];
    float* s0 = sm;               // G -> cholG (kept for L)
    float* s1 = sm + SLOT;        // X0 -> cholX -> F_c -> W (rotated)
    float* s2 = sm + 2 * SLOT;    // F_b
    float* fv  = sm + 3 * SLOT;   // 64
    float* cb  = fv + 64;         // 32
    float* sb  = cb + 32;         // 32
    int*   pqb = (int*)(sb + 32); // 32
    float* red = sb + 64;         // 24
    float* vec = red + 24;        // 64
    float* nrm = vec + 64;        // 64
    const int tid = threadIdx.x;
    const int b  = blockIdx.x;
    const int nb = b >> 3, pp = b & 7;
    const int c0 = (pp & 1) + ((pp >> 1) << 2);  // {0,1,4,5,8,9,12,13}
    const float* X0 = x + (size_t)(nb * 16 + c0) * 4096;
    const float* X1 = X0 + 2 * 4096;
    const float w0 = g_w01[0], w1 = g_w01[1];

    // s0 = G = w0*X0 + w1*X1 ; s1 = X0
    for (int i = tid; i < 4096; i += 256) {
        float v0 = X0[i], v1 = X1[i];
        int r = i >> 6, c = i & 63;
        s0[r * LD + c] = w0 * v0 + w1 * v1;
        s1[r * LD + c] = v0;
    }
    __syncthreads();

    chol_u(s0);                           // G = Ltil_G D_G Ltil_G^T
    chol_u(s1);                           // X0 = Ltil_X D_X Ltil_X^T
    // fv = D_X; build Lx = Ltil_X D_X^{1/2} in place (zero upper)
    if (tid < 64) fv[tid] = s1[tid * 66];
    __syncthreads();
    for (int i = tid; i < 4096; i += 256) {
        int r = i >> 6, c = i & 63;
        float d = fmaxf(fv[c], 1e-30f);
        float v = (c < r) ? s1[r * LD + c] * rsqrtf(d)
                          : ((c == r) ? sqrtf(d) : 0.0f);
        s1[r * LD + c] = v;
    }
    __syncthreads();
    trsm_left(s0, s1);                    // s1 = Ltil_G^{-1} Lx
    if (tid < 64) vec[tid] = rsqrtf(fmaxf(s0[tid * 66], 1e-30f));
    __syncthreads();
    for (int i = tid; i < 4096; i += 256) {
        int r = i >> 6, c = i & 63;
        s1[r * LD + c] *= vec[r];         // F_c = D_G^{-1/2} (...)
    }
    __syncthreads();

    jacobi1s(s1, nrm, cb, sb, pqb, red);  // columns -> u_i sqrt(l_i)

    // fv[i] = sqrt(g_i / l_i),  g_i = a^w0 b^w1, a = l_i, b = (1-w0 a)/w1
    if (tid < 64) {
        float a = fmaxf(nrm[tid], 1e-12f);
        float bb = fmaxf((1.0f - w0 * a) / w1, 1e-12f);
        float g = expf(w0 * logf(a) + w1 * logf(bb));
        fv[tid] = sqrtf(g / a);
    }
    __syncthreads();
    for (int i = tid; i < 4096; i += 256) {
        int r = i >> 6, c = i & 63;
        s1[r * LD + c] *= fv[c];          // W' = W diag(sqrt(g/l))
    }
    __syncthreads();
    mm_ltn(s2, s0, vec, s1);              // F_b = L_G W'
    // write factor + bary
    float* fb = g_fbuf + (size_t)b * 4096;
    for (int i = tid; i < 4096; i += 256)
        fb[i] = s2[(i >> 6) * LD + (i & 63)];
    mm_nt_g(g_abuf + (size_t)b * 4096, s2, s2);   // bary = F_b F_b^T
}

// ---------------------------------------------------------------------------
// means over 4096 matrices: 2-stage deterministic
// ---------------------------------------------------------------------------
__global__ void k_meanA_s1() {
    const int e = blockIdx.x * 256 + threadIdx.x;
    const int m0 = blockIdx.y * 512;
    float s = 0.0f;
    #pragma unroll 8
    for (int m = 0; m < 512; ++m) s += g_abuf[(size_t)(m0 + m) * 4096 + e];
    g_part[blockIdx.y * 4096 + e] = s;
}
__global__ void k_meanA_s2() {
    const int e = blockIdx.x * 256 + threadIdx.x;
    float s = 0.0f;
    #pragma unroll
    for (int w = 0; w < 8; ++w) s += g_part[w * 4096 + e];
    g_G0[e] = s * (1.0f / 4096.0f);
}
__global__ void k_meanL_s1() {
    const int e = blockIdx.x * 256 + threadIdx.x;
    const int m0 = blockIdx.y * 512;
    float s = 0.0f;
    #pragma unroll 8
    for (int m = 0; m < 512; ++m) s += g_lbuf[(size_t)(m0 + m) * 4096 + e];
    g_part[blockIdx.y * 4096 + e] = s;
}
__global__ void k_meanL_s2() {
    const int e = blockIdx.x * 256 + threadIdx.x;
    float s = 0.0f;
    #pragma unroll
    for (int w = 0; w < 8; ++w) s += g_part[w * 4096 + e];
    g_Sbar[e] = s * (1.0f / 4096.0f);
}

// ---------------------------------------------------------------------------
// K4: Cholesky of G0 -> dense L0 and L0^{-1} (single block)
// ---------------------------------------------------------------------------
__global__ void __launch_bounds__(256, 1) k_g0() {
    extern __shared__ float sm[];
    float* s0 = sm;
    float* s1 = sm + SLOT;
    const int tid = threadIdx.x;
    gload(s0, g_G0);
    chol_u(s0);
    for (int i = tid; i < 4096; i += 256) {
        int r = i >> 6, c = i & 63;
        float d = fmaxf(s0[c * 66], 1e-30f);
        float v = (c < r) ? s0[r * LD + c] * rsqrtf(d)
                          : ((c == r) ? sqrtf(d) : 0.0f);
        g_L0[i] = v;
        s1[r * LD + c] = (r == c) ? 1.0f : 0.0f;
    }
    __syncthreads();
    trsm_left(s0, s1);
    for (int i = tid; i < 4096; i += 256) {
        int r = i >> 6, c = i & 63;
        g_Li0[i] = rsqrtf(fmaxf(s0[r * 66], 1e-30f)) * s1[r * LD + c];
    }
}

// ---------------------------------------------------------------------------
// K5: L_m = logm((Li0 F_b)(Li0 F_b)^T) via one-sided Jacobi. grid=4096.
// ---------------------------------------------------------------------------
__global__ void __launch_bounds__(256, 4) k_bn1() {
    extern __shared__ float sm[];
    float* s0 = sm;               // Li0
    float* s1 = sm + SLOT;        // F_b
    float* s2 = sm + 2 * SLOT;    // Fm = Li0 F_b -> W
    float* fv  = sm + 3 * SLOT;
    float* cb  = fv + 64;
    float* sb  = cb + 32;
    int*   pqb = (int*)(sb + 32);
    float* red = sb + 64;
    float* vec = red + 24;
    float* nrm = vec + 64;
    const int tid = threadIdx.x;
    const int m = blockIdx.x;
    gload(s0, g_Li0);
    gload(s1, g_fbuf + (size_t)m * 4096);
    mm_nn(s2, s0, s1);            // factor of Li0 bary Li0^T
    jacobi1s(s2, nrm, cb, sb, pqb, red);
    if (tid < 64) {
        float l = fmaxf(nrm[tid], 1e-12f);
        fv[tid] = logf(l) / l;
    }
    __syncthreads();
    mm_recon_g(g_lbuf + (size_t)m * 4096, s2, fv);
    (void)vec;
}

// ---------------------------------------------------------------------------
// K7: bary = L0 expm(Sbar) L0^T; T = bnw^{1/2} @ bary^{-1/2}. single block.
// ---------------------------------------------------------------------------
__global__ void __launch_bounds__(256, 1) k_bary(const float* __restrict__ bnw) {
    extern __shared__ float sm[];
    float* s0 = sm;
    float* s1 = sm + SLOT;
    float* s2 = sm + 2 * SLOT;
    float* s3 = sm + 3 * SLOT;
    float* red = sm + 4 * SLOT;
    float* vec = red + 24;
    const int tid = threadIdx.x;

    gload(s0, g_Sbar);
    sexpm(s0, s1, s2, red);          // s1 = E = expm(Sbar)
    gload(s0, g_L0);
    mm_nn(s2, s0, s1);               // L0 * E
    mm_nt(s1, s2, s0);               // s1 = bary
    float lam = spec_est(s1, vec, red);
    float csc = 1.15f * lam, ic = 1.0f / csc;
    for (int i = tid; i < 4096; i += 256) {
        int r = i >> 6, c = i & 63;
        s1[r * LD + c] *= ic;
        s3[r * LD + c] = (r == c) ? 1.0f : 0.0f;
    }
    __syncthreads();
    ns_sqrt(s1, s3, s2, red);        // s3 = (bary/c)^{-1/2}
    float irc = rsqrtf(csc);
    for (int i = tid; i < 4096; i += 256) {
        int r = i >> 6, c = i & 63;
        s3[r * LD + c] *= irc;
    }
    __syncthreads();
    gload(s0, bnw);
    float lam2 = spec_est(s0, vec, red);
    float c2 = 1.15f * lam2, ic2 = 1.0f / c2;
    for (int i = tid; i < 4096; i += 256) {
        int r = i >> 6, c = i & 63;
        s0[r * LD + c] *= ic2;
        s1[r * LD + c] = (r == c) ? 1.0f : 0.0f;
    }
    __syncthreads();
    ns_sqrt(s0, s1, s2, red);        // s0 = (bnw/c2)^{1/2}
    float rc2 = sqrtf(c2);
    for (int i = tid; i < 4096; i += 256) {
        int r = i >> 6, c = i & 63;
        s0[r * LD + c] *= rc2;       // Ws
    }
    __syncthreads();
    mm_nn_g(g_T, s0, s3);            // T = Ws @ bary^{-1/2}
}

// ---------------------------------------------------------------------------
// K8: out = T M T^T (ReEig clamp provably inactive).
// ---------------------------------------------------------------------------
__global__ void __launch_bounds__(256, 4) k_out(float* __restrict__ out) {
    extern __shared__ float sm[];
    float* MG = sm;
    float* MA = sm + SLOT;
    float* MT = sm + 2 * SLOT;
    const int m = blockIdx.x;
    gload(MG, g_T);
    gload(MA, g_abuf + (size_t)m * 4096);
    mm_nn(MT, MG, MA);
    mm_nt_g(out + (size_t)m * 4096, MT, MG);
}

// ---------------------------------------------------------------------------
extern "C" void kernel_launch(void* const* d_in, const int* in_sizes, int n_in,
                              void* d_out, int out_size) {
    const float* x   = (const float*)d_in[0];
    const float* w1  = (const float*)d_in[1];
    const float* bnw = (const float*)d_in[2];
    float* out = (float*)d_out;

    const int sm4t = (4 * SLOT + TAIL) * (int)sizeof(float);
    const int sm3t = (3 * SLOT + TAIL) * (int)sizeof(float);
    const int sm3  = (3 * SLOT) * (int)sizeof(float);
    const int sm2  = (2 * SLOT) * (int)sizeof(float);

    cudaFuncSetAttribute(k_pair, cudaFuncAttributeMaxDynamicSharedMemorySize, sm3t);
    cudaFuncSetAttribute(k_g0,   cudaFuncAttributeMaxDynamicSharedMemorySize, sm2);
    cudaFuncSetAttribute(k_bn1,  cudaFuncAttributeMaxDynamicSharedMemorySize, sm3t);
    cudaFuncSetAttribute(k_bary, cudaFuncAttributeMaxDynamicSharedMemorySize, sm4t);
    cudaFuncSetAttribute(k_out,  cudaFuncAttributeMaxDynamicSharedMemorySize, sm3);

    k_softmax<<<1, 1>>>(w1);
    k_pair<<<4096, 256, sm3t>>>(x);
    k_meanA_s1<<<dim3(16, 8), 256>>>();
    k_meanA_s2<<<16, 256>>>();
    k_g0<<<1, 256, sm2>>>();
    k_bn1<<<4096, 256, sm3t>>>();
    k_meanL_s1<<<dim3(16, 8), 256>>>();
    k_meanL_s2<<<16, 256>>>();
    k_bary<<<1, 256, sm4t>>>(bnw);
    k_out<<<4096, 256, sm3>>>(out);
    (void)in_sizes; (void)n_in; (void)out_size;
}

// round 11
// speedup vs baseline: 2.8710x; 2.8710x over previous
#include <cuda_runtime.h>
#include <math.h>

// ---------------------------------------------------------------------------
// DiMap SPD pipeline, round 10.
// Register-resident one-sided Jacobi, circle-method layout: position 0 fixed,
// ring positions 1..63 shift each round, so pair indices are LITERAL register
// positions ((0,63),(k,63-k)) and the round-robin is a compile-time register
// renaming. No lookup table, no computed register indices.
// ---------------------------------------------------------------------------

#define LD 65
#define SLOT (64 * LD)
#define TAIL 384
#define MAXSWEEP 10
#define JTOL1S 1e-5f
#define NSMAX 13

// --- scratch ---------------------------------------------------------------
__device__ float g_abuf[16777216];   // bary matrices
__device__ float g_fbuf[16777216];   // bary factors
__device__ float g_lbuf[16777216];   // log matrices
__device__ float g_cbuf[16777216];   // eig factor (in/out of k_eig)
__device__ float g_glbuf[16777216];  // per-pair dense L_G
__device__ float g_lam[262144];      // 4096 x 64 eigenvalues
__device__ float g_part[32768];
__device__ float g_w01[2];
__device__ float g_G0[4096];
__device__ float g_Sbar[4096];
__device__ float g_L0[4096];
__device__ float g_Li0[4096];
__device__ float g_T[4096];

// ---------------------------------------------------------------------------
__device__ float block_sum(float v, float* red) {
    const int tid = threadIdx.x;
    #pragma unroll
    for (int o = 16; o > 0; o >>= 1) v += __shfl_xor_sync(0xFFFFFFFFu, v, o);
    __syncthreads();
    if ((tid & 31) == 0) red[tid >> 5] = v;
    __syncthreads();
    if (tid == 0) {
        float s = 0.0f;
        #pragma unroll
        for (int w = 0; w < 8; ++w) s += red[w];
        red[8] = s;
    }
    __syncthreads();
    float r = red[8];
    __syncthreads();
    return r;
}

__device__ float spec_est(const float* A, float* vec, float* red) {
    const int tid = threadIdx.x;
    if (tid < 64) vec[tid] = 1.0f;
    __syncthreads();
    float m = 1.0f;
    for (int it = 0; it < 6; ++it) {
        float y = 0.0f;
        if (tid < 64) {
            #pragma unroll 8
            for (int k = 0; k < 64; ++k) y += A[tid * LD + k] * vec[k];
            float a = fabsf(y);
            #pragma unroll
            for (int o = 16; o > 0; o >>= 1)
                a = fmaxf(a, __shfl_xor_sync(0xFFFFFFFFu, a, o));
            if ((tid & 31) == 0) red[tid >> 5] = a;
        }
        __syncthreads();
        m = fmaxf(red[0], red[1]);
        if (tid < 64) vec[tid] = y / m;
        __syncthreads();
    }
    return m;
}

// ---------------------------------------------------------------------------
// Unscaled LDL^T Cholesky / trsm (256 threads)
// ---------------------------------------------------------------------------
__device__ void chol_u(float* W) {
    const int tid = threadIdx.x;
    for (int j = 0; j < 64; ++j) {
        float dinv = 1.0f / W[j * LD + j];
        #pragma unroll
        for (int it = 0; it < 16; ++it) {
            int i = tid + it * 256;
            int r = i >> 6, c = i & 63;
            if (r > j && c > j)
                W[r * LD + c] -= W[r * LD + j] * W[c * LD + j] * dinv;
        }
        __syncthreads();
    }
}

__device__ void trsm_left(const float* W, float* X) {
    const int tid = threadIdx.x;
    for (int i = 0; i < 64; ++i) {
        float dinv = 1.0f / W[i * LD + i];
        #pragma unroll
        for (int it = 0; it < 16; ++it) {
            int idx = tid + it * 256;
            int r = idx >> 6, c = idx & 63;
            if (r > i)
                X[r * LD + c] -= (W[r * LD + i] * dinv) * X[i * LD + c];
        }
        __syncthreads();
    }
}

// ---------------------------------------------------------------------------
// 64x64 matmuls (256 threads, 4x4 tiles). In-place C==A or C==B is safe.
// ---------------------------------------------------------------------------
__device__ void mm_nn(float* C, const float* A, const float* B) {
    const int t = threadIdx.x;
    const int i0 = (t >> 4) << 2, j0 = (t & 15) << 2;
    float acc[4][4];
    #pragma unroll
    for (int r = 0; r < 4; ++r)
        #pragma unroll
        for (int c = 0; c < 4; ++c) acc[r][c] = 0.0f;
    #pragma unroll 4
    for (int k = 0; k < 64; ++k) {
        float a[4], b[4];
        #pragma unroll
        for (int r = 0; r < 4; ++r) a[r] = A[(i0 + r) * LD + k];
        #pragma unroll
        for (int c = 0; c < 4; ++c) b[c] = B[k * LD + j0 + c];
        #pragma unroll
        for (int r = 0; r < 4; ++r)
            #pragma unroll
            for (int c = 0; c < 4; ++c) acc[r][c] += a[r] * b[c];
    }
    __syncthreads();
    #pragma unroll
    for (int r = 0; r < 4; ++r)
        #pragma unroll
        for (int c = 0; c < 4; ++c) C[(i0 + r) * LD + j0 + c] = acc[r][c];
    __syncthreads();
}

__device__ void mm_nt(float* C, const float* A, const float* B) {
    const int t = threadIdx.x;
    const int i0 = (t >> 4) << 2, j0 = (t & 15) << 2;
    float acc[4][4];
    #pragma unroll
    for (int r = 0; r < 4; ++r)
        #pragma unroll
        for (int c = 0; c < 4; ++c) acc[r][c] = 0.0f;
    #pragma unroll 4
    for (int k = 0; k < 64; ++k) {
        float a[4], b[4];
        #pragma unroll
        for (int r = 0; r < 4; ++r) a[r] = A[(i0 + r) * LD + k];
        #pragma unroll
        for (int c = 0; c < 4; ++c) b[c] = B[(j0 + c) * LD + k];
        #pragma unroll
        for (int r = 0; r < 4; ++r)
            #pragma unroll
            for (int c = 0; c < 4; ++c) acc[r][c] += a[r] * b[c];
    }
    __syncthreads();
    #pragma unroll
    for (int r = 0; r < 4; ++r)
        #pragma unroll
        for (int c = 0; c < 4; ++c) C[(i0 + r) * LD + j0 + c] = acc[r][c];
    __syncthreads();
}

__device__ void mm_nn_g(float* Cg, const float* A, const float* B) {
    const int t = threadIdx.x;
    const int i0 = (t >> 4) << 2, j0 = (t & 15) << 2;
    float acc[4][4];
    #pragma unroll
    for (int r = 0; r < 4; ++r)
        #pragma unroll
        for (int c = 0; c < 4; ++c) acc[r][c] = 0.0f;
    #pragma unroll 4
    for (int k = 0; k < 64; ++k) {
        float a[4], b[4];
        #pragma unroll
        for (int r = 0; r < 4; ++r) a[r] = A[(i0 + r) * LD + k];
        #pragma unroll
        for (int c = 0; c < 4; ++c) b[c] = B[k * LD + j0 + c];
        #pragma unroll
        for (int r = 0; r < 4; ++r)
            #pragma unroll
            for (int c = 0; c < 4; ++c) acc[r][c] += a[r] * b[c];
    }
    #pragma unroll
    for (int r = 0; r < 4; ++r)
        #pragma unroll
        for (int c = 0; c < 4; ++c) Cg[(i0 + r) * 64 + j0 + c] = acc[r][c];
    __syncthreads();
}

__device__ void mm_nt_g(float* Cg, const float* A, const float* B) {
    const int t = threadIdx.x;
    const int i0 = (t >> 4) << 2, j0 = (t & 15) << 2;
    float acc[4][4];
    #pragma unroll
    for (int r = 0; r < 4; ++r)
        #pragma unroll
        for (int c = 0; c < 4; ++c) acc[r][c] = 0.0f;
    #pragma unroll 4
    for (int k = 0; k < 64; ++k) {
        float a[4], b[4];
        #pragma unroll
        for (int r = 0; r < 4; ++r) a[r] = A[(i0 + r) * LD + k];
        #pragma unroll
        for (int c = 0; c < 4; ++c) b[c] = B[(j0 + c) * LD + k];
        #pragma unroll
        for (int r = 0; r < 4; ++r)
            #pragma unroll
            for (int c = 0; c < 4; ++c) acc[r][c] += a[r] * b[c];
    }
    #pragma unroll
    for (int r = 0; r < 4; ++r)
        #pragma unroll
        for (int c = 0; c < 4; ++c) Cg[(i0 + r) * 64 + j0 + c] = acc[r][c];
    __syncthreads();
}

// Cg(gmem) = V diag(f) V^T
__device__ void mm_recon_g(float* Cg, const float* V, const float* f) {
    const int t = threadIdx.x;
    const int i0 = (t >> 4) << 2, j0 = (t & 15) << 2;
    float acc[4][4];
    #pragma unroll
    for (int r = 0; r < 4; ++r)
        #pragma unroll
        for (int c = 0; c < 4; ++c) acc[r][c] = 0.0f;
    #pragma unroll 4
    for (int k = 0; k < 64; ++k) {
        float fk = f[k];
        float a[4], b[4];
        #pragma unroll
        for (int r = 0; r < 4; ++r) a[r] = V[(i0 + r) * LD + k] * fk;
        #pragma unroll
        for (int c = 0; c < 4; ++c) b[c] = V[(j0 + c) * LD + k];
        #pragma unroll
        for (int r = 0; r < 4; ++r)
            #pragma unroll
            for (int c = 0; c < 4; ++c) acc[r][c] += a[r] * b[c];
    }
    #pragma unroll
    for (int r = 0; r < 4; ++r)
        #pragma unroll
        for (int c = 0; c < 4; ++c) Cg[(i0 + r) * 64 + j0 + c] = acc[r][c];
    __syncthreads();
}

__device__ void gload(float* M, const float* g) {
    for (int i = threadIdx.x; i < 4096; i += 256)
        M[(i >> 6) * LD + (i & 63)] = g[i];
    __syncthreads();
}

// ---------------------------------------------------------------------------
// NS + sexpm (k_bary only)
// ---------------------------------------------------------------------------
__device__ void ns_sqrt(float* Y, float* Z, float* T, float* red) {
    const int tid = threadIdx.x;
    for (int it = 0; it < NSMAX; ++it) {
        mm_nn(T, Z, Y);
        float mx = 0.0f;
        for (int i = tid; i < 4096; i += 256) {
            int r = i >> 6, c = i & 63;
            float v = T[r * LD + c];
            float t = ((r == c) ? 1.5f : 0.0f) - 0.5f * v;
            T[r * LD + c] = t;
            mx = fmaxf(mx, fabsf(t - ((r == c) ? 1.0f : 0.0f)));
        }
        __syncthreads();
        #pragma unroll
        for (int o = 16; o > 0; o >>= 1)
            mx = fmaxf(mx, __shfl_xor_sync(0xFFFFFFFFu, mx, o));
        if ((tid & 31) == 0) red[tid >> 5] = mx;
        __syncthreads();
        if (tid == 0) {
            float g = 0.0f;
            #pragma unroll
            for (int w = 0; w < 8; ++w) g = fmaxf(g, red[w]);
            red[8] = g;
        }
        __syncthreads();
        float g = red[8];
        __syncthreads();
        if (g < 3e-8f) break;
        mm_nn(Y, Y, T);
        mm_nn(Z, T, Z);
    }
}

__device__ void sexpm(float* B, float* Q, float* T, float* red) {
    const int tid = threadIdx.x;
    float s2 = 0.0f;
    for (int i = tid; i < 4096; i += 256) {
        float v = B[(i >> 6) * LD + (i & 63)];
        s2 += v * v;
    }
    float fn = sqrtf(block_sum(s2, red));
    int s = 0; float f = fn;
    while (f > 0.5f && s < 40) { f *= 0.5f; ++s; }
    float scale = ldexpf(1.0f, -s);
    for (int i = tid; i < 4096; i += 256)
        B[(i >> 6) * LD + (i & 63)] *= scale;
    __syncthreads();
    for (int i = tid; i < 4096; i += 256) {
        int r = i >> 6, c = i & 63;
        Q[r * LD + c] = ((r == c) ? 1.0f : 0.0f) + 0.1f * B[r * LD + c];
    }
    __syncthreads();
    for (int k = 9; k >= 1; --k) {
        mm_nn(T, B, Q);
        float inv = 1.0f / (float)k;
        for (int i = tid; i < 4096; i += 256) {
            int r = i >> 6, c = i & 63;
            Q[r * LD + c] = ((r == c) ? 1.0f : 0.0f) + inv * T[r * LD + c];
        }
        __syncthreads();
    }
    for (int i = 0; i < s; ++i) mm_nn(Q, Q, Q);
}

// ---------------------------------------------------------------------------
__global__ void k_softmax(const float* __restrict__ wv) {
    float a = wv[0], b = wv[1];
    float m = fmaxf(a, b);
    float ea = expf(a - m), eb = expf(b - m);
    float inv = 1.0f / (ea + eb);
    g_w01[0] = ea * inv;
    g_w01[1] = eb * inv;
}

// ---------------------------------------------------------------------------
// k_eig: register-resident one-sided Jacobi, circle-method positions.
// 64 threads; thread r holds row r of the factor in w[0..63] (by POSITION).
// Pairs every round: (0,63) and (k, 63-k), k=1..31 — literal indices.
// After each round the ring (positions 1..63) shifts by one (register
// renaming). Ring returns to identity after 63 rounds (one sweep).
// ---------------------------------------------------------------------------
__global__ void __launch_bounds__(64) k_eig() {
    __shared__ float sm[64 * 65];
    __shared__ float nrm[64];   // column norms by POSITION
    __shared__ float cbuf[32];
    __shared__ float sbuf[32];
    __shared__ float flag;
    const int r = threadIdx.x;
    const int m = blockIdx.x;
    float* gb = g_cbuf + (size_t)m * 4096;

    // staged coalesced load: sm[a*65+b] = W[a][b]
    #pragma unroll
    for (int it = 0; it < 64; ++it)
        sm[it * 65 + r] = gb[it * 64 + r];
    __syncthreads();
    {   // initial column norms
        float s = 0.0f;
        #pragma unroll
        for (int a = 0; a < 64; ++a) { float v = sm[a * 65 + r]; s += v * v; }
        nrm[r] = s;
    }
    float w[64];
    #pragma unroll
    for (int j = 0; j < 64; ++j) w[j] = sm[r * 65 + j];
    __syncthreads();

    #pragma unroll 1
    for (int sw = 0; sw < MAXSWEEP; ++sw) {
        float gacc = 0.0f;
        #pragma unroll
        for (int rnd = 0; rnd < 63; ++rnd) {
            // products for the 32 position-pairs (literal indices)
            sm[0 * 65 + r] = w[0] * w[63];
            #pragma unroll
            for (int k = 1; k < 32; ++k)
                sm[k * 65 + r] = w[k] * w[63 - k];
            __syncthreads();
            // angles: lane k handles pair k (warp 0 only)
            if (r < 32) {
                float gam = 0.0f;
                #pragma unroll
                for (int a = 0; a < 64; ++a) gam += sm[r * 65 + a];
                const int A = (r == 0) ? 0 : r;
                const int B = (r == 0) ? 63 : 63 - r;
                float al = nrm[A], be = nrm[B];
                float c = 1.0f, s = 0.0f;
                if (fabsf(gam) > 1e-37f) {
                    float tau = (be - al) / (2.0f * gam);
                    float t = copysignf(1.0f, tau) /
                              (fabsf(tau) + sqrtf(1.0f + tau * tau));
                    c = rsqrtf(1.0f + t * t);
                    s = t * c;
                    float cs = c * s;
                    float nal = c * c * al - 2.0f * cs * gam + s * s * be;
                    float nbe = s * s * al + 2.0f * cs * gam + c * c * be;
                    al = nal; be = nbe;
                }
                __syncwarp();
                // write norms to POST-SHIFT positions:
                // sigma(0)=0, sigma(i)=i+1 (1<=i<=62), sigma(63)=1
                const int sA = (r == 0) ? 0 : r + 1;
                const int sB = (r == 0) ? 1 : 64 - r;
                nrm[sA] = al;
                nrm[sB] = be;
                cbuf[r] = c; sbuf[r] = s;
                gacc += gam * gam;
            }
            __syncthreads();
            // rotate pairs in registers (literal indices), then shift ring
            {
                float c0 = cbuf[0], s0 = sbuf[0];
                float vp = w[0], vq = w[63];
                w[0]  = c0 * vp - s0 * vq;
                w[63] = s0 * vp + c0 * vq;
            }
            #pragma unroll
            for (int k = 1; k < 32; ++k) {
                float c = cbuf[k], s = sbuf[k];
                float vp = w[k], vq = w[63 - k];
                w[k]      = c * vp - s * vq;
                w[63 - k] = s * vp + c * vq;
            }
            // ring shift: content of position i -> i+1, 63 -> 1 (renaming)
            {
                float tmp = w[63];
                #pragma unroll
                for (int i = 62; i >= 1; --i) w[i + 1] = w[i];
                w[1] = tmp;
            }
        }
        // convergence: sum gamma^2 this sweep vs sum lambda^2
        if (r < 32) {
            float tot = gacc;
            float d = nrm[r] * nrm[r] + nrm[r + 32] * nrm[r + 32];
            #pragma unroll
            for (int o = 16; o > 0; o >>= 1) {
                tot += __shfl_xor_sync(0xFFFFFFFFu, tot, o);
                d   += __shfl_xor_sync(0xFFFFFFFFu, d, o);
            }
            if (r == 0) flag = (tot <= JTOL1S * d + 1e-30f) ? 1.0f : 0.0f;
        }
        __syncthreads();
        if (flag != 0.0f) break;
    }

    // store rotated rows; exact eigenvalues; coalesced write-back
    #pragma unroll
    for (int j = 0; j < 64; ++j) sm[r * 65 + j] = w[j];
    __syncthreads();
    {
        float s = 0.0f;
        #pragma unroll
        for (int a = 0; a < 64; ++a) { float v = sm[a * 65 + r]; s += v * v; }
        g_lam[(size_t)m * 64 + r] = s;
    }
    #pragma unroll
    for (int it = 0; it < 64; ++it)
        gb[it * 64 + r] = sm[it * 65 + r];
}

// ---------------------------------------------------------------------------
// k_pair_pre: chol(G), chol(X0), trsm -> F_c (g_cbuf) and dense L_G (g_glbuf)
// ---------------------------------------------------------------------------
__global__ void __launch_bounds__(256, 4) k_pair_pre(const float* __restrict__ x) {
    extern __shared__ float sm[];
    float* s0 = sm;               // G -> cholG
    float* s1 = sm + SLOT;        // X0 -> cholX -> F_c
    float* fv  = sm + 2 * SLOT;   // 64
    float* vec = fv + 64;         // 64
    const int tid = threadIdx.x;
    const int b  = blockIdx.x;
    const int nb = b >> 3, pp = b & 7;
    const int c0 = (pp & 1) + ((pp >> 1) << 2);
    const float* X0 = x + (size_t)(nb * 16 + c0) * 4096;
    const float* X1 = X0 + 2 * 4096;
    const float w0 = g_w01[0], w1 = g_w01[1];

    for (int i = tid; i < 4096; i += 256) {
        float v0 = X0[i], v1 = X1[i];
        int r = i >> 6, c = i & 63;
        s0[r * LD + c] = w0 * v0 + w1 * v1;
        s1[r * LD + c] = v0;
    }
    __syncthreads();
    chol_u(s0);
    chol_u(s1);
    if (tid < 64) fv[tid] = s1[tid * 66];
    __syncthreads();
    for (int i = tid; i < 4096; i += 256) {
        int r = i >> 6, c = i & 63;
        float d = fmaxf(fv[c], 1e-30f);
        float v = (c < r) ? s1[r * LD + c] * rsqrtf(d)
                          : ((c == r) ? sqrtf(d) : 0.0f);
        s1[r * LD + c] = v;                    // Lx
    }
    __syncthreads();
    trsm_left(s0, s1);                         // Ltil_G^{-1} Lx
    if (tid < 64) vec[tid] = rsqrtf(fmaxf(s0[tid * 66], 1e-30f));
    __syncthreads();
    for (int i = tid; i < 4096; i += 256) {
        int r = i >> 6, c = i & 63;
        g_cbuf[(size_t)b * 4096 + i] = s1[r * LD + c] * vec[r];
        float d = fmaxf(s0[c * 66], 1e-30f);
        float lv = (c < r) ? s0[r * LD + c] * rsqrtf(d)
                           : ((c == r) ? sqrtf(d) : 0.0f);
        g_glbuf[(size_t)b * 4096 + i] = lv;
    }
}

// ---------------------------------------------------------------------------
// k_pair_post: F_b = L_G W diag(sqrt(g/l)); bary = F_b F_b^T
// ---------------------------------------------------------------------------
__global__ void __launch_bounds__(256, 4) k_pair_post() {
    extern __shared__ float sm[];
    float* s0 = sm;               // L_G
    float* s1 = sm + SLOT;        // W -> F_b
    float* fv = sm + 2 * SLOT;    // 64
    const int tid = threadIdx.x;
    const int b = blockIdx.x;
    const float w0 = g_w01[0], w1 = g_w01[1];
    gload(s0, g_glbuf + (size_t)b * 4096);
    gload(s1, g_cbuf + (size_t)b * 4096);
    if (tid < 64) {
        float a = fmaxf(g_lam[(size_t)b * 64 + tid], 1e-12f);
        float bb = fmaxf((1.0f - w0 * a) / w1, 1e-12f);
        float g = expf(w0 * logf(a) + w1 * logf(bb));
        fv[tid] = sqrtf(g / a);
    }
    __syncthreads();
    for (int i = tid; i < 4096; i += 256) {
        int r = i >> 6, c = i & 63;
        s1[r * LD + c] *= fv[c];
    }
    __syncthreads();
    mm_nn(s1, s0, s1);            // F_b (in-place on B)
    float* fb = g_fbuf + (size_t)b * 4096;
    for (int i = tid; i < 4096; i += 256)
        fb[i] = s1[(i >> 6) * LD + (i & 63)];
    mm_nt_g(g_abuf + (size_t)b * 4096, s1, s1);
}

// ---------------------------------------------------------------------------
// means: 2-stage deterministic
// ---------------------------------------------------------------------------
__global__ void k_meanA_s1() {
    const int e = blockIdx.x * 256 + threadIdx.x;
    const int m0 = blockIdx.y * 512;
    float s = 0.0f;
    #pragma unroll 8
    for (int m = 0; m < 512; ++m) s += g_abuf[(size_t)(m0 + m) * 4096 + e];
    g_part[blockIdx.y * 4096 + e] = s;
}
__global__ void k_meanA_s2() {
    const int e = blockIdx.x * 256 + threadIdx.x;
    float s = 0.0f;
    #pragma unroll
    for (int w = 0; w < 8; ++w) s += g_part[w * 4096 + e];
    g_G0[e] = s * (1.0f / 4096.0f);
}
__global__ void k_meanL_s1() {
    const int e = blockIdx.x * 256 + threadIdx.x;
    const int m0 = blockIdx.y * 512;
    float s = 0.0f;
    #pragma unroll 8
    for (int m = 0; m < 512; ++m) s += g_lbuf[(size_t)(m0 + m) * 4096 + e];
    g_part[blockIdx.y * 4096 + e] = s;
}
__global__ void k_meanL_s2() {
    const int e = blockIdx.x * 256 + threadIdx.x;
    float s = 0.0f;
    #pragma unroll
    for (int w = 0; w < 8; ++w) s += g_part[w * 4096 + e];
    g_Sbar[e] = s * (1.0f / 4096.0f);
}

// ---------------------------------------------------------------------------
// K4: Cholesky of G0 -> dense L0 and L0^{-1} (single block)
// ---------------------------------------------------------------------------
__global__ void __launch_bounds__(256, 1) k_g0() {
    extern __shared__ float sm[];
    float* s0 = sm;
    float* s1 = sm + SLOT;
    const int tid = threadIdx.x;
    gload(s0, g_G0);
    chol_u(s0);
    for (int i = tid; i < 4096; i += 256) {
        int r = i >> 6, c = i & 63;
        float d = fmaxf(s0[c * 66], 1e-30f);
        float v = (c < r) ? s0[r * LD + c] * rsqrtf(d)
                          : ((c == r) ? sqrtf(d) : 0.0f);
        g_L0[i] = v;
        s1[r * LD + c] = (r == c) ? 1.0f : 0.0f;
    }
    __syncthreads();
    trsm_left(s0, s1);
    for (int i = tid; i < 4096; i += 256) {
        int r = i >> 6, c = i & 63;
        g_Li0[i] = rsqrtf(fmaxf(s0[r * 66], 1e-30f)) * s1[r * LD + c];
    }
}

// ---------------------------------------------------------------------------
// k_bn1_pre: Fm = Li0 F_b -> g_cbuf
// ---------------------------------------------------------------------------
__global__ void __launch_bounds__(256, 4) k_bn1_pre() {
    extern __shared__ float sm[];
    float* s0 = sm;
    float* s1 = sm + SLOT;
    const int tid = threadIdx.x;
    const int m = blockIdx.x;
    gload(s0, g_Li0);
    gload(s1, g_fbuf + (size_t)m * 4096);
    mm_nn(s1, s0, s1);            // in-place
    for (int i = tid; i < 4096; i += 256)
        g_cbuf[(size_t)m * 4096 + i] = s1[(i >> 6) * LD + (i & 63)];
}

// ---------------------------------------------------------------------------
// k_bn1_post: L_m = W diag(log l / l) W^T -> g_lbuf
// ---------------------------------------------------------------------------
__global__ void __launch_bounds__(256, 4) k_bn1_post() {
    extern __shared__ float sm[];
    float* s1 = sm;
    float* fv = sm + SLOT;
    const int tid = threadIdx.x;
    const int m = blockIdx.x;
    gload(s1, g_cbuf + (size_t)m * 4096);
    if (tid < 64) {
        float l = fmaxf(g_lam[(size_t)m * 64 + tid], 1e-12f);
        fv[tid] = logf(l) / l;
    }
    __syncthreads();
    mm_recon_g(g_lbuf + (size_t)m * 4096, s1, fv);
}

// ---------------------------------------------------------------------------
// K7: bary = L0 expm(Sbar) L0^T; T = bnw^{1/2} @ bary^{-1/2}. single block.
// ---------------------------------------------------------------------------
__global__ void __launch_bounds__(256, 1) k_bary(const float* __restrict__ bnw) {
    extern __shared__ float sm[];
    float* s0 = sm;
    float* s1 = sm + SLOT;
    float* s2 = sm + 2 * SLOT;
    float* s3 = sm + 3 * SLOT;
    float* red = sm + 4 * SLOT;
    float* vec = red + 24;
    const int tid = threadIdx.x;

    gload(s0, g_Sbar);
    sexpm(s0, s1, s2, red);
    gload(s0, g_L0);
    mm_nn(s2, s0, s1);
    mm_nt(s1, s2, s0);               // bary
    float lam = spec_est(s1, vec, red);
    float csc = 1.15f * lam, ic = 1.0f / csc;
    for (int i = tid; i < 4096; i += 256) {
        int r = i >> 6, c = i & 63;
        s1[r * LD + c] *= ic;
        s3[r * LD + c] = (r == c) ? 1.0f : 0.0f;
    }
    __syncthreads();
    ns_sqrt(s1, s3, s2, red);
    float irc = rsqrtf(csc);
    for (int i = tid; i < 4096; i += 256) {
        int r = i >> 6, c = i & 63;
        s3[r * LD + c] *= irc;       // bary^{-1/2}
    }
    __syncthreads();
    gload(s0, bnw);
    float lam2 = spec_est(s0, vec, red);
    float c2 = 1.15f * lam2, ic2 = 1.0f / c2;
    for (int i = tid; i < 4096; i += 256) {
        int r = i >> 6, c = i & 63;
        s0[r * LD + c] *= ic2;
        s1[r * LD + c] = (r == c) ? 1.0f : 0.0f;
    }
    __syncthreads();
    ns_sqrt(s0, s1, s2, red);
    float rc2 = sqrtf(c2);
    for (int i = tid; i < 4096; i += 256) {
        int r = i >> 6, c = i & 63;
        s0[r * LD + c] *= rc2;       // Ws
    }
    __syncthreads();
    mm_nn_g(g_T, s0, s3);            // T
}

// ---------------------------------------------------------------------------
// K8: out = T M T^T
// ---------------------------------------------------------------------------
__global__ void __launch_bounds__(256, 4) k_out(float* __restrict__ out) {
    extern __shared__ float sm[];
    float* MG = sm;
    float* MA = sm + SLOT;
    float* MT = sm + 2 * SLOT;
    const int m = blockIdx.x;
    gload(MG, g_T);
    gload(MA, g_abuf + (size_t)m * 4096);
    mm_nn(MT, MG, MA);
    mm_nt_g(out + (size_t)m * 4096, MT, MG);
}

// ---------------------------------------------------------------------------
extern "C" void kernel_launch(void* const* d_in, const int* in_sizes, int n_in,
                              void* d_out, int out_size) {
    const float* x   = (const float*)d_in[0];
    const float* w1  = (const float*)d_in[1];
    const float* bnw = (const float*)d_in[2];
    float* out = (float*)d_out;

    const int sm4t = (4 * SLOT + TAIL) * (int)sizeof(float);
    const int sm3  = (3 * SLOT) * (int)sizeof(float);
    const int sm2t = (2 * SLOT + TAIL) * (int)sizeof(float);
    const int sm2  = (2 * SLOT) * (int)sizeof(float);

    cudaFuncSetAttribute(k_pair_pre,  cudaFuncAttributeMaxDynamicSharedMemorySize, sm2t);
    cudaFuncSetAttribute(k_pair_post, cudaFuncAttributeMaxDynamicSharedMemorySize, sm2t);
    cudaFuncSetAttribute(k_g0,        cudaFuncAttributeMaxDynamicSharedMemorySize, sm2);
    cudaFuncSetAttribute(k_bn1_pre,   cudaFuncAttributeMaxDynamicSharedMemorySize, sm2);
    cudaFuncSetAttribute(k_bn1_post,  cudaFuncAttributeMaxDynamicSharedMemorySize, sm2t);
    cudaFuncSetAttribute(k_bary,      cudaFuncAttributeMaxDynamicSharedMemorySize, sm4t);
    cudaFuncSetAttribute(k_out,       cudaFuncAttributeMaxDynamicSharedMemorySize, sm3);

    k_softmax<<<1, 1>>>(w1);
    k_pair_pre<<<4096, 256, sm2t>>>(x);
    k_eig<<<4096, 64>>>();
    k_pair_post<<<4096, 256, sm2t>>>();
    k_meanA_s1<<<dim3(16, 8), 256>>>();
    k_meanA_s2<<<16, 256>>>();
    k_g0<<<1, 256, sm2>>>();
    k_bn1_pre<<<4096, 256, sm2>>>();
    k_eig<<<4096, 64>>>();
    k_bn1_post<<<4096, 256, sm2t>>>();
    k_meanL_s1<<<dim3(16, 8), 256>>>();
    k_meanL_s2<<<16, 256>>>();
    k_bary<<<1, 256, sm4t>>>(bnw);
    k_out<<<4096, 256, sm3>>>(out);
    (void)in_sizes; (void)n_in; (void)out_size;
}

// round 12
// speedup vs baseline: 3.4322x; 1.1954x over previous
#include <cuda_runtime.h>
#include <math.h>

// ---------------------------------------------------------------------------
// DiMap SPD pipeline, round 11.
// R10 (register-resident circle-method one-sided Jacobi) +
//  - triangular, row-skipped Cholesky (lower triangle only; iteration loop
//    starts at the first live row block); dual-matrix fused chol in k_pair_pre
//  - row-skipped trsm
//  - JTOL1S 1e-5 -> 1e-4 (start-of-sweep metric is quadratically pessimistic)
// ---------------------------------------------------------------------------

#define LD 65
#define SLOT (64 * LD)
#define TAIL 384
#define MAXSWEEP 10
#define JTOL1S 1e-4f
#define NSMAX 13

// --- scratch ---------------------------------------------------------------
__device__ float g_abuf[16777216];   // bary matrices
__device__ float g_fbuf[16777216];   // bary factors
__device__ float g_lbuf[16777216];   // log matrices
__device__ float g_cbuf[16777216];   // eig factor (in/out of k_eig)
__device__ float g_glbuf[16777216];  // per-pair dense L_G
__device__ float g_lam[262144];      // 4096 x 64 eigenvalues
__device__ float g_part[32768];
__device__ float g_w01[2];
__device__ float g_G0[4096];
__device__ float g_Sbar[4096];
__device__ float g_L0[4096];
__device__ float g_Li0[4096];
__device__ float g_T[4096];

// ---------------------------------------------------------------------------
__device__ float block_sum(float v, float* red) {
    const int tid = threadIdx.x;
    #pragma unroll
    for (int o = 16; o > 0; o >>= 1) v += __shfl_xor_sync(0xFFFFFFFFu, v, o);
    __syncthreads();
    if ((tid & 31) == 0) red[tid >> 5] = v;
    __syncthreads();
    if (tid == 0) {
        float s = 0.0f;
        #pragma unroll
        for (int w = 0; w < 8; ++w) s += red[w];
        red[8] = s;
    }
    __syncthreads();
    float r = red[8];
    __syncthreads();
    return r;
}

__device__ float spec_est(const float* A, float* vec, float* red) {
    const int tid = threadIdx.x;
    if (tid < 64) vec[tid] = 1.0f;
    __syncthreads();
    float m = 1.0f;
    for (int it = 0; it < 6; ++it) {
        float y = 0.0f;
        if (tid < 64) {
            #pragma unroll 8
            for (int k = 0; k < 64; ++k) y += A[tid * LD + k] * vec[k];
            float a = fabsf(y);
            #pragma unroll
            for (int o = 16; o > 0; o >>= 1)
                a = fmaxf(a, __shfl_xor_sync(0xFFFFFFFFu, a, o));
            if ((tid & 31) == 0) red[tid >> 5] = a;
        }
        __syncthreads();
        m = fmaxf(red[0], red[1]);
        if (tid < 64) vec[tid] = y / m;
        __syncthreads();
    }
    return m;
}

// ---------------------------------------------------------------------------
// Unscaled LDL^T Cholesky, LOWER TRIANGLE ONLY, row-skipped iteration start.
// Exit (lower + diag): W[r][j] (r>j) = Ltil[r][j]*D[j]; W[j][j] = D[j].
// Upper triangle is left stale — no downstream consumer reads it.
// ---------------------------------------------------------------------------
__device__ void chol_u(float* W) {
    const int tid = threadIdx.x;
    for (int j = 0; j < 64; ++j) {
        float dinv = 1.0f / W[j * LD + j];
        for (int it = j >> 2; it < 16; ++it) {
            int i = tid + it * 256;
            int r = i >> 6, c = i & 63;
            if (r > j && c > j && c <= r)
                W[r * LD + c] -= W[r * LD + j] * W[c * LD + j] * dinv;
        }
        __syncthreads();
    }
}

// dual-matrix fused variant: same barriers, both matrices per step
__device__ void chol_u2(float* W0, float* W1) {
    const int tid = threadIdx.x;
    for (int j = 0; j < 64; ++j) {
        float d0 = 1.0f / W0[j * LD + j];
        float d1 = 1.0f / W1[j * LD + j];
        for (int it = j >> 2; it < 16; ++it) {
            int i = tid + it * 256;
            int r = i >> 6, c = i & 63;
            if (r > j && c > j && c <= r) {
                W0[r * LD + c] -= W0[r * LD + j] * W0[c * LD + j] * d0;
                W1[r * LD + c] -= W1[r * LD + j] * W1[c * LD + j] * d1;
            }
        }
        __syncthreads();
    }
}

// X <- Ltil^{-1} X (unit-lower factors packed in W, lower+diag), row-skipped
__device__ void trsm_left(const float* W, float* X) {
    const int tid = threadIdx.x;
    for (int i = 0; i < 64; ++i) {
        float dinv = 1.0f / W[i * LD + i];
        for (int it = i >> 2; it < 16; ++it) {
            int idx = tid + it * 256;
            int r = idx >> 6, c = idx & 63;
            if (r > i)
                X[r * LD + c] -= (W[r * LD + i] * dinv) * X[i * LD + c];
        }
        __syncthreads();
    }
}

// ---------------------------------------------------------------------------
// 64x64 matmuls (256 threads, 4x4 tiles). In-place C==A or C==B is safe.
// ---------------------------------------------------------------------------
__device__ void mm_nn(float* C, const float* A, const float* B) {
    const int t = threadIdx.x;
    const int i0 = (t >> 4) << 2, j0 = (t & 15) << 2;
    float acc[4][4];
    #pragma unroll
    for (int r = 0; r < 4; ++r)
        #pragma unroll
        for (int c = 0; c < 4; ++c) acc[r][c] = 0.0f;
    #pragma unroll 4
    for (int k = 0; k < 64; ++k) {
        float a[4], b[4];
        #pragma unroll
        for (int r = 0; r < 4; ++r) a[r] = A[(i0 + r) * LD + k];
        #pragma unroll
        for (int c = 0; c < 4; ++c) b[c] = B[k * LD + j0 + c];
        #pragma unroll
        for (int r = 0; r < 4; ++r)
            #pragma unroll
            for (int c = 0; c < 4; ++c) acc[r][c] += a[r] * b[c];
    }
    __syncthreads();
    #pragma unroll
    for (int r = 0; r < 4; ++r)
        #pragma unroll
        for (int c = 0; c < 4; ++c) C[(i0 + r) * LD + j0 + c] = acc[r][c];
    __syncthreads();
}

__device__ void mm_nt(float* C, const float* A, const float* B) {
    const int t = threadIdx.x;
    const int i0 = (t >> 4) << 2, j0 = (t & 15) << 2;
    float acc[4][4];
    #pragma unroll
    for (int r = 0; r < 4; ++r)
        #pragma unroll
        for (int c = 0; c < 4; ++c) acc[r][c] = 0.0f;
    #pragma unroll 4
    for (int k = 0; k < 64; ++k) {
        float a[4], b[4];
        #pragma unroll
        for (int r = 0; r < 4; ++r) a[r] = A[(i0 + r) * LD + k];
        #pragma unroll
        for (int c = 0; c < 4; ++c) b[c] = B[(j0 + c) * LD + k];
        #pragma unroll
        for (int r = 0; r < 4; ++r)
            #pragma unroll
            for (int c = 0; c < 4; ++c) acc[r][c] += a[r] * b[c];
    }
    __syncthreads();
    #pragma unroll
    for (int r = 0; r < 4; ++r)
        #pragma unroll
        for (int c = 0; c < 4; ++c) C[(i0 + r) * LD + j0 + c] = acc[r][c];
    __syncthreads();
}

__device__ void mm_nn_g(float* Cg, const float* A, const float* B) {
    const int t = threadIdx.x;
    const int i0 = (t >> 4) << 2, j0 = (t & 15) << 2;
    float acc[4][4];
    #pragma unroll
    for (int r = 0; r < 4; ++r)
        #pragma unroll
        for (int c = 0; c < 4; ++c) acc[r][c] = 0.0f;
    #pragma unroll 4
    for (int k = 0; k < 64; ++k) {
        float a[4], b[4];
        #pragma unroll
        for (int r = 0; r < 4; ++r) a[r] = A[(i0 + r) * LD + k];
        #pragma unroll
        for (int c = 0; c < 4; ++c) b[c] = B[k * LD + j0 + c];
        #pragma unroll
        for (int r = 0; r < 4; ++r)
            #pragma unroll
            for (int c = 0; c < 4; ++c) acc[r][c] += a[r] * b[c];
    }
    #pragma unroll
    for (int r = 0; r < 4; ++r)
        #pragma unroll
        for (int c = 0; c < 4; ++c) Cg[(i0 + r) * 64 + j0 + c] = acc[r][c];
    __syncthreads();
}

__device__ void mm_nt_g(float* Cg, const float* A, const float* B) {
    const int t = threadIdx.x;
    const int i0 = (t >> 4) << 2, j0 = (t & 15) << 2;
    float acc[4][4];
    #pragma unroll
    for (int r = 0; r < 4; ++r)
        #pragma unroll
        for (int c = 0; c < 4; ++c) acc[r][c] = 0.0f;
    #pragma unroll 4
    for (int k = 0; k < 64; ++k) {
        float a[4], b[4];
        #pragma unroll
        for (int r = 0; r < 4; ++r) a[r] = A[(i0 + r) * LD + k];
        #pragma unroll
        for (int c = 0; c < 4; ++c) b[c] = B[(j0 + c) * LD + k];
        #pragma unroll
        for (int r = 0; r < 4; ++r)
            #pragma unroll
            for (int c = 0; c < 4; ++c) acc[r][c] += a[r] * b[c];
    }
    #pragma unroll
    for (int r = 0; r < 4; ++r)
        #pragma unroll
        for (int c = 0; c < 4; ++c) Cg[(i0 + r) * 64 + j0 + c] = acc[r][c];
    __syncthreads();
}

// Cg(gmem) = V diag(f) V^T
__device__ void mm_recon_g(float* Cg, const float* V, const float* f) {
    const int t = threadIdx.x;
    const int i0 = (t >> 4) << 2, j0 = (t & 15) << 2;
    float acc[4][4];
    #pragma unroll
    for (int r = 0; r < 4; ++r)
        #pragma unroll
        for (int c = 0; c < 4; ++c) acc[r][c] = 0.0f;
    #pragma unroll 4
    for (int k = 0; k < 64; ++k) {
        float fk = f[k];
        float a[4], b[4];
        #pragma unroll
        for (int r = 0; r < 4; ++r) a[r] = V[(i0 + r) * LD + k] * fk;
        #pragma unroll
        for (int c = 0; c < 4; ++c) b[c] = V[(j0 + c) * LD + k];
        #pragma unroll
        for (int r = 0; r < 4; ++r)
            #pragma unroll
            for (int c = 0; c < 4; ++c) acc[r][c] += a[r] * b[c];
    }
    #pragma unroll
    for (int r = 0; r < 4; ++r)
        #pragma unroll
        for (int c = 0; c < 4; ++c) Cg[(i0 + r) * 64 + j0 + c] = acc[r][c];
    __syncthreads();
}

__device__ void gload(float* M, const float* g) {
    for (int i = threadIdx.x; i < 4096; i += 256)
        M[(i >> 6) * LD + (i & 63)] = g[i];
    __syncthreads();
}

// ---------------------------------------------------------------------------
// NS + sexpm (k_bary only)
// ---------------------------------------------------------------------------
__device__ void ns_sqrt(float* Y, float* Z, float* T, float* red) {
    const int tid = threadIdx.x;
    for (int it = 0; it < NSMAX; ++it) {
        mm_nn(T, Z, Y);
        float mx = 0.0f;
        for (int i = tid; i < 4096; i += 256) {
            int r = i >> 6, c = i & 63;
            float v = T[r * LD + c];
            float t = ((r == c) ? 1.5f : 0.0f) - 0.5f * v;
            T[r * LD + c] = t;
            mx = fmaxf(mx, fabsf(t - ((r == c) ? 1.0f : 0.0f)));
        }
        __syncthreads();
        #pragma unroll
        for (int o = 16; o > 0; o >>= 1)
            mx = fmaxf(mx, __shfl_xor_sync(0xFFFFFFFFu, mx, o));
        if ((tid & 31) == 0) red[tid >> 5] = mx;
        __syncthreads();
        if (tid == 0) {
            float g = 0.0f;
            #pragma unroll
            for (int w = 0; w < 8; ++w) g = fmaxf(g, red[w]);
            red[8] = g;
        }
        __syncthreads();
        float g = red[8];
        __syncthreads();
        if (g < 3e-8f) break;
        mm_nn(Y, Y, T);
        mm_nn(Z, T, Z);
    }
}

__device__ void sexpm(float* B, float* Q, float* T, float* red) {
    const int tid = threadIdx.x;
    float s2 = 0.0f;
    for (int i = tid; i < 4096; i += 256) {
        float v = B[(i >> 6) * LD + (i & 63)];
        s2 += v * v;
    }
    float fn = sqrtf(block_sum(s2, red));
    int s = 0; float f = fn;
    while (f > 0.5f && s < 40) { f *= 0.5f; ++s; }
    float scale = ldexpf(1.0f, -s);
    for (int i = tid; i < 4096; i += 256)
        B[(i >> 6) * LD + (i & 63)] *= scale;
    __syncthreads();
    for (int i = tid; i < 4096; i += 256) {
        int r = i >> 6, c = i & 63;
        Q[r * LD + c] = ((r == c) ? 1.0f : 0.0f) + 0.1f * B[r * LD + c];
    }
    __syncthreads();
    for (int k = 9; k >= 1; --k) {
        mm_nn(T, B, Q);
        float inv = 1.0f / (float)k;
        for (int i = tid; i < 4096; i += 256) {
            int r = i >> 6, c = i & 63;
            Q[r * LD + c] = ((r == c) ? 1.0f : 0.0f) + inv * T[r * LD + c];
        }
        __syncthreads();
    }
    for (int i = 0; i < s; ++i) mm_nn(Q, Q, Q);
}

// ---------------------------------------------------------------------------
__global__ void k_softmax(const float* __restrict__ wv) {
    float a = wv[0], b = wv[1];
    float m = fmaxf(a, b);
    float ea = expf(a - m), eb = expf(b - m);
    float inv = 1.0f / (ea + eb);
    g_w01[0] = ea * inv;
    g_w01[1] = eb * inv;
}

// ---------------------------------------------------------------------------
// k_eig: register-resident one-sided Jacobi, circle-method positions.
// (unchanged from R10 except JTOL1S)
// ---------------------------------------------------------------------------
__global__ void __launch_bounds__(64) k_eig() {
    __shared__ float sm[64 * 65];
    __shared__ float nrm[64];
    __shared__ float cbuf[32];
    __shared__ float sbuf[32];
    __shared__ float flag;
    const int r = threadIdx.x;
    const int m = blockIdx.x;
    float* gb = g_cbuf + (size_t)m * 4096;

    #pragma unroll
    for (int it = 0; it < 64; ++it)
        sm[it * 65 + r] = gb[it * 64 + r];
    __syncthreads();
    {
        float s = 0.0f;
        #pragma unroll
        for (int a = 0; a < 64; ++a) { float v = sm[a * 65 + r]; s += v * v; }
        nrm[r] = s;
    }
    float w[64];
    #pragma unroll
    for (int j = 0; j < 64; ++j) w[j] = sm[r * 65 + j];
    __syncthreads();

    #pragma unroll 1
    for (int sw = 0; sw < MAXSWEEP; ++sw) {
        float gacc = 0.0f;
        #pragma unroll
        for (int rnd = 0; rnd < 63; ++rnd) {
            sm[0 * 65 + r] = w[0] * w[63];
            #pragma unroll
            for (int k = 1; k < 32; ++k)
                sm[k * 65 + r] = w[k] * w[63 - k];
            __syncthreads();
            if (r < 32) {
                float gam = 0.0f;
                #pragma unroll
                for (int a = 0; a < 64; ++a) gam += sm[r * 65 + a];
                const int A = (r == 0) ? 0 : r;
                const int B = (r == 0) ? 63 : 63 - r;
                float al = nrm[A], be = nrm[B];
                float c = 1.0f, s = 0.0f;
                if (fabsf(gam) > 1e-37f) {
                    float tau = (be - al) / (2.0f * gam);
                    float t = copysignf(1.0f, tau) /
                              (fabsf(tau) + sqrtf(1.0f + tau * tau));
                    c = rsqrtf(1.0f + t * t);
                    s = t * c;
                    float cs = c * s;
                    float nal = c * c * al - 2.0f * cs * gam + s * s * be;
                    float nbe = s * s * al + 2.0f * cs * gam + c * c * be;
                    al = nal; be = nbe;
                }
                __syncwarp();
                const int sA = (r == 0) ? 0 : r + 1;
                const int sB = (r == 0) ? 1 : 64 - r;
                nrm[sA] = al;
                nrm[sB] = be;
                cbuf[r] = c; sbuf[r] = s;
                gacc += gam * gam;
            }
            __syncthreads();
            {
                float c0 = cbuf[0], s0 = sbuf[0];
                float vp = w[0], vq = w[63];
                w[0]  = c0 * vp - s0 * vq;
                w[63] = s0 * vp + c0 * vq;
            }
            #pragma unroll
            for (int k = 1; k < 32; ++k) {
                float c = cbuf[k], s = sbuf[k];
                float vp = w[k], vq = w[63 - k];
                w[k]      = c * vp - s * vq;
                w[63 - k] = s * vp + c * vq;
            }
            {
                float tmp = w[63];
                #pragma unroll
                for (int i = 62; i >= 1; --i) w[i + 1] = w[i];
                w[1] = tmp;
            }
        }
        if (r < 32) {
            float tot = gacc;
            float d = nrm[r] * nrm[r] + nrm[r + 32] * nrm[r + 32];
            #pragma unroll
            for (int o = 16; o > 0; o >>= 1) {
                tot += __shfl_xor_sync(0xFFFFFFFFu, tot, o);
                d   += __shfl_xor_sync(0xFFFFFFFFu, d, o);
            }
            if (r == 0) flag = (tot <= JTOL1S * d + 1e-30f) ? 1.0f : 0.0f;
        }
        __syncthreads();
        if (flag != 0.0f) break;
    }

    #pragma unroll
    for (int j = 0; j < 64; ++j) sm[r * 65 + j] = w[j];
    __syncthreads();
    {
        float s = 0.0f;
        #pragma unroll
        for (int a = 0; a < 64; ++a) { float v = sm[a * 65 + r]; s += v * v; }
        g_lam[(size_t)m * 64 + r] = s;
    }
    #pragma unroll
    for (int it = 0; it < 64; ++it)
        gb[it * 64 + r] = sm[it * 65 + r];
}

// ---------------------------------------------------------------------------
// k_pair_pre: dual chol(G, X0), trsm -> F_c (g_cbuf) and dense L_G (g_glbuf)
// ---------------------------------------------------------------------------
__global__ void __launch_bounds__(256, 4) k_pair_pre(const float* __restrict__ x) {
    extern __shared__ float sm[];
    float* s0 = sm;               // G -> cholG
    float* s1 = sm + SLOT;        // X0 -> cholX -> F_c
    float* fv  = sm + 2 * SLOT;   // 64
    float* vec = fv + 64;         // 64
    const int tid = threadIdx.x;
    const int b  = blockIdx.x;
    const int nb = b >> 3, pp = b & 7;
    const int c0 = (pp & 1) + ((pp >> 1) << 2);
    const float* X0 = x + (size_t)(nb * 16 + c0) * 4096;
    const float* X1 = X0 + 2 * 4096;
    const float w0 = g_w01[0], w1 = g_w01[1];

    for (int i = tid; i < 4096; i += 256) {
        float v0 = X0[i], v1 = X1[i];
        int r = i >> 6, c = i & 63;
        s0[r * LD + c] = w0 * v0 + w1 * v1;
        s1[r * LD + c] = v0;
    }
    __syncthreads();
    chol_u2(s0, s1);              // both factorizations, shared barriers
    if (tid < 64) fv[tid] = s1[tid * 66];
    __syncthreads();
    for (int i = tid; i < 4096; i += 256) {
        int r = i >> 6, c = i & 63;
        float d = fmaxf(fv[c], 1e-30f);
        float v = (c < r) ? s1[r * LD + c] * rsqrtf(d)
                          : ((c == r) ? sqrtf(d) : 0.0f);
        s1[r * LD + c] = v;                    // Lx (upper zeroed)
    }
    __syncthreads();
    trsm_left(s0, s1);                         // Ltil_G^{-1} Lx
    if (tid < 64) vec[tid] = rsqrtf(fmaxf(s0[tid * 66], 1e-30f));
    __syncthreads();
    for (int i = tid; i < 4096; i += 256) {
        int r = i >> 6, c = i & 63;
        g_cbuf[(size_t)b * 4096 + i] = s1[r * LD + c] * vec[r];
        float d = fmaxf(s0[c * 66], 1e-30f);
        float lv = (c < r) ? s0[r * LD + c] * rsqrtf(d)
                           : ((c == r) ? sqrtf(d) : 0.0f);
        g_glbuf[(size_t)b * 4096 + i] = lv;
    }
}

// ---------------------------------------------------------------------------
// k_pair_post: F_b = L_G W diag(sqrt(g/l)); bary = F_b F_b^T
// ---------------------------------------------------------------------------
__global__ void __launch_bounds__(256, 4) k_pair_post() {
    extern __shared__ float sm[];
    float* s0 = sm;               // L_G
    float* s1 = sm + SLOT;        // W -> F_b
    float* fv = sm + 2 * SLOT;    // 64
    const int tid = threadIdx.x;
    const int b = blockIdx.x;
    const float w0 = g_w01[0], w1 = g_w01[1];
    gload(s0, g_glbuf + (size_t)b * 4096);
    gload(s1, g_cbuf + (size_t)b * 4096);
    if (tid < 64) {
        float a = fmaxf(g_lam[(size_t)b * 64 + tid], 1e-12f);
        float bb = fmaxf((1.0f - w0 * a) / w1, 1e-12f);
        float g = expf(w0 * logf(a) + w1 * logf(bb));
        fv[tid] = sqrtf(g / a);
    }
    __syncthreads();
    for (int i = tid; i < 4096; i += 256) {
        int r = i >> 6, c = i & 63;
        s1[r * LD + c] *= fv[c];
    }
    __syncthreads();
    mm_nn(s1, s0, s1);            // F_b (in-place on B)
    float* fb = g_fbuf + (size_t)b * 4096;
    for (int i = tid; i < 4096; i += 256)
        fb[i] = s1[(i >> 6) * LD + (i & 63)];
    mm_nt_g(g_abuf + (size_t)b * 4096, s1, s1);
}

// ---------------------------------------------------------------------------
// means: 2-stage deterministic
// ---------------------------------------------------------------------------
__global__ void k_meanA_s1() {
    const int e = blockIdx.x * 256 + threadIdx.x;
    const int m0 = blockIdx.y * 512;
    float s = 0.0f;
    #pragma unroll 8
    for (int m = 0; m < 512; ++m) s += g_abuf[(size_t)(m0 + m) * 4096 + e];
    g_part[blockIdx.y * 4096 + e] = s;
}
__global__ void k_meanA_s2() {
    const int e = blockIdx.x * 256 + threadIdx.x;
    float s = 0.0f;
    #pragma unroll
    for (int w = 0; w < 8; ++w) s += g_part[w * 4096 + e];
    g_G0[e] = s * (1.0f / 4096.0f);
}
__global__ void k_meanL_s1() {
    const int e = blockIdx.x * 256 + threadIdx.x;
    const int m0 = blockIdx.y * 512;
    float s = 0.0f;
    #pragma unroll 8
    for (int m = 0; m < 512; ++m) s += g_lbuf[(size_t)(m0 + m) * 4096 + e];
    g_part[blockIdx.y * 4096 + e] = s;
}
__global__ void k_meanL_s2() {
    const int e = blockIdx.x * 256 + threadIdx.x;
    float s = 0.0f;
    #pragma unroll
    for (int w = 0; w < 8; ++w) s += g_part[w * 4096 + e];
    g_Sbar[e] = s * (1.0f / 4096.0f);
}

// ---------------------------------------------------------------------------
// K4: Cholesky of G0 -> dense L0 and L0^{-1} (single block)
// ---------------------------------------------------------------------------
__global__ void __launch_bounds__(256, 1) k_g0() {
    extern __shared__ float sm[];
    float* s0 = sm;
    float* s1 = sm + SLOT;
    const int tid = threadIdx.x;
    gload(s0, g_G0);
    chol_u(s0);
    for (int i = tid; i < 4096; i += 256) {
        int r = i >> 6, c = i & 63;
        float d = fmaxf(s0[c * 66], 1e-30f);
        float v = (c < r) ? s0[r * LD + c] * rsqrtf(d)
                          : ((c == r) ? sqrtf(d) : 0.0f);
        g_L0[i] = v;
        s1[r * LD + c] = (r == c) ? 1.0f : 0.0f;
    }
    __syncthreads();
    trsm_left(s0, s1);
    for (int i = tid; i < 4096; i += 256) {
        int r = i >> 6, c = i & 63;
        g_Li0[i] = rsqrtf(fmaxf(s0[r * 66], 1e-30f)) * s1[r * LD + c];
    }
}

// ---------------------------------------------------------------------------
// k_bn1_pre: Fm = Li0 F_b -> g_cbuf
// ---------------------------------------------------------------------------
__global__ void __launch_bounds__(256, 4) k_bn1_pre() {
    extern __shared__ float sm[];
    float* s0 = sm;
    float* s1 = sm + SLOT;
    const int tid = threadIdx.x;
    const int m = blockIdx.x;
    gload(s0, g_Li0);
    gload(s1, g_fbuf + (size_t)m * 4096);
    mm_nn(s1, s0, s1);
    for (int i = tid; i < 4096; i += 256)
        g_cbuf[(size_t)m * 4096 + i] = s1[(i >> 6) * LD + (i & 63)];
}

// ---------------------------------------------------------------------------
// k_bn1_post: L_m = W diag(log l / l) W^T -> g_lbuf
// ---------------------------------------------------------------------------
__global__ void __launch_bounds__(256, 4) k_bn1_post() {
    extern __shared__ float sm[];
    float* s1 = sm;
    float* fv = sm + SLOT;
    const int tid = threadIdx.x;
    const int m = blockIdx.x;
    gload(s1, g_cbuf + (size_t)m * 4096);
    if (tid < 64) {
        float l = fmaxf(g_lam[(size_t)m * 64 + tid], 1e-12f);
        fv[tid] = logf(l) / l;
    }
    __syncthreads();
    mm_recon_g(g_lbuf + (size_t)m * 4096, s1, fv);
}

// ---------------------------------------------------------------------------
// K7: bary = L0 expm(Sbar) L0^T; T = bnw^{1/2} @ bary^{-1/2}. single block.
// ---------------------------------------------------------------------------
__global__ void __launch_bounds__(256, 1) k_bary(const float* __restrict__ bnw) {
    extern __shared__ float sm[];
    float* s0 = sm;
    float* s1 = sm + SLOT;
    float* s2 = sm + 2 * SLOT;
    float* s3 = sm + 3 * SLOT;
    float* red = sm + 4 * SLOT;
    float* vec = red + 24;
    const int tid = threadIdx.x;

    gload(s0, g_Sbar);
    sexpm(s0, s1, s2, red);
    gload(s0, g_L0);
    mm_nn(s2, s0, s1);
    mm_nt(s1, s2, s0);               // bary
    float lam = spec_est(s1, vec, red);
    float csc = 1.15f * lam, ic = 1.0f / csc;
    for (int i = tid; i < 4096; i += 256) {
        int r = i >> 6, c = i & 63;
        s1[r * LD + c] *= ic;
        s3[r * LD + c] = (r == c) ? 1.0f : 0.0f;
    }
    __syncthreads();
    ns_sqrt(s1, s3, s2, red);
    float irc = rsqrtf(csc);
    for (int i = tid; i < 4096; i += 256) {
        int r = i >> 6, c = i & 63;
        s3[r * LD + c] *= irc;       // bary^{-1/2}
    }
    __syncthreads();
    gload(s0, bnw);
    float lam2 = spec_est(s0, vec, red);
    float c2 = 1.15f * lam2, ic2 = 1.0f / c2;
    for (int i = tid; i < 4096; i += 256) {
        int r = i >> 6, c = i & 63;
        s0[r * LD + c] *= ic2;
        s1[r * LD + c] = (r == c) ? 1.0f : 0.0f;
    }
    __syncthreads();
    ns_sqrt(s0, s1, s2, red);
    float rc2 = sqrtf(c2);
    for (int i = tid; i < 4096; i += 256) {
        int r = i >> 6, c = i & 63;
        s0[r * LD + c] *= rc2;       // Ws
    }
    __syncthreads();
    mm_nn_g(g_T, s0, s3);            // T
}

// ---------------------------------------------------------------------------
// K8: out = T M T^T
// ---------------------------------------------------------------------------
__global__ void __launch_bounds__(256, 4) k_out(float* __restrict__ out) {
    extern __shared__ float sm[];
    float* MG = sm;
    float* MA = sm + SLOT;
    float* MT = sm + 2 * SLOT;
    const int m = blockIdx.x;
    gload(MG, g_T);
    gload(MA, g_abuf + (size_t)m * 4096);
    mm_nn(MT, MG, MA);
    mm_nt_g(out + (size_t)m * 4096, MT, MG);
}

// ---------------------------------------------------------------------------
extern "C" void kernel_launch(void* const* d_in, const int* in_sizes, int n_in,
                              void* d_out, int out_size) {
    const float* x   = (const float*)d_in[0];
    const float* w1  = (const float*)d_in[1];
    const float* bnw = (const float*)d_in[2];
    float* out = (float*)d_out;

    const int sm4t = (4 * SLOT + TAIL) * (int)sizeof(float);
    const int sm3  = (3 * SLOT) * (int)sizeof(float);
    const int sm2t = (2 * SLOT + TAIL) * (int)sizeof(float);
    const int sm2  = (2 * SLOT) * (int)sizeof(float);

    cudaFuncSetAttribute(k_pair_pre,  cudaFuncAttributeMaxDynamicSharedMemorySize, sm2t);
    cudaFuncSetAttribute(k_pair_post, cudaFuncAttributeMaxDynamicSharedMemorySize, sm2t);
    cudaFuncSetAttribute(k_g0,        cudaFuncAttributeMaxDynamicSharedMemorySize, sm2);
    cudaFuncSetAttribute(k_bn1_pre,   cudaFuncAttributeMaxDynamicSharedMemorySize, sm2);
    cudaFuncSetAttribute(k_bn1_post,  cudaFuncAttributeMaxDynamicSharedMemorySize, sm2t);
    cudaFuncSetAttribute(k_bary,      cudaFuncAttributeMaxDynamicSharedMemorySize, sm4t);
    cudaFuncSetAttribute(k_out,       cudaFuncAttributeMaxDynamicSharedMemorySize, sm3);

    k_softmax<<<1, 1>>>(w1);
    k_pair_pre<<<4096, 256, sm2t>>>(x);
    k_eig<<<4096, 64>>>();
    k_pair_post<<<4096, 256, sm2t>>>();
    k_meanA_s1<<<dim3(16, 8), 256>>>();
    k_meanA_s2<<<16, 256>>>();
    k_g0<<<1, 256, sm2>>>();
    k_bn1_pre<<<4096, 256, sm2>>>();
    k_eig<<<4096, 64>>>();
    k_bn1_post<<<4096, 256, sm2t>>>();
    k_meanL_s1<<<dim3(16, 8), 256>>>();
    k_meanL_s2<<<16, 256>>>();
    k_bary<<<1, 256, sm4t>>>(bnw);
    k_out<<<4096, 256, sm3>>>(out);
    (void)in_sizes; (void)n_in; (void)out_size;
}